// round 9
// baseline (speedup 1.0000x reference)
#include <cuda_runtime.h>
#include <math_constants.h>

// ChamferLoss via exact grid NN. One warp per query; flattened 3x3x3 union
// scan with forced MLP=4; packed per-cell neighborhood ranges (one 8B load
// per row). Launch order puts k_query at user-launch index 3 (ncu slot).
// d2min(p -> Q) = |p|^2 - 2 * max_j ( p.q_j - 0.5|q_j|^2 )
//
// 16 structures: s in [0,8) nonfiltered (0-3 pn, 4-7 gn, 8192 pts),
//                s in [8,16) filtered (8-11 pf, 12-15 gf, 4096 pts).
// Structure s queries partner s^4.
//
// Exactness: after scanning the full (clamped) index cube of radius r, any
// unscanned point lies beyond a scanned face; stop when bd2 <= (0.9999*b)^2.
// Clamped/duplicated cells rescan candidates; max is idempotent -> harmless.

#define G     32
#define NCELL (G * G * G)
#define H     0.32f
#define INVH  3.125f
#define RANGE 5.12f
#define NSTRUCT 16
#define CAP   8192

#define NQ_TOTAL 98304
#define QWARPS   4
#define QBLK     (QWARPS * 32)
#define QBLOCKS  (NQ_TOTAL / QWARPS)
#define FBLK     512

__device__ int    g_cnt  [NSTRUCT * NCELL];   // zero at load; re-zeroed by k_final
__device__ int    g_start[NSTRUCT * NCELL];
__device__ int    g_cur  [NSTRUCT * NCELL];   // after scatter: end of each cell
__device__ int2   g_nbr  [NSTRUCT * NCELL];   // (start[x-1 cl], end[x+1 cl]) per cell
__device__ float4 g_pts  [NSTRUCT * CAP];
__device__ float  g_blocksum[QBLOCKS];

__device__ __forceinline__ int cell_coord(float x) {
    int c = (int)floorf((x + RANGE) * INVH);
    return min(max(c, 0), G - 1);
}

__device__ __forceinline__ const float* map_point(
    int t, const float* pf, const float* gf, const float* pn, const float* gn,
    int* idx, int* s)
{
    if (t < 65536) {
        const int grp = t >> 13;
        *idx = t & 8191;
        *s   = grp;
        return ((grp < 4) ? pn : gn) + (size_t)(grp & 3) * 8192 * 3;
    } else {
        const int tf  = t - 65536;
        const int grp = tf >> 12;
        *idx = tf & 4095;
        *s   = 8 + grp;
        return ((grp < 4) ? pf : gf) + (size_t)(grp & 3) * 4096 * 3;
    }
}

__global__ __launch_bounds__(256) void k_count(
    const float* __restrict__ pf, const float* __restrict__ gf,
    const float* __restrict__ pn, const float* __restrict__ gn)
{
    const int t = blockIdx.x * 256 + threadIdx.x;
    int i, s;
    const float* P = map_point(t, pf, gf, pn, gn, &i, &s);
    const float x = P[3 * i], y = P[3 * i + 1], z = P[3 * i + 2];
    const int cell = (cell_coord(z) * G + cell_coord(y)) * G + cell_coord(x);
    atomicAdd(&g_cnt[s * NCELL + cell], 1);
}

__global__ __launch_bounds__(1024) void k_scan() {
    const int s   = blockIdx.x;
    const int tid = threadIdx.x;
    const int CPT = NCELL / 1024;          // 32 cells per thread
    const int base = s * NCELL + tid * CPT;

    int cnt[CPT];
    int sum = 0;
    #pragma unroll
    for (int k = 0; k < CPT; k++) { cnt[k] = g_cnt[base + k]; sum += cnt[k]; }

    __shared__ int sh[1024];
    sh[tid] = sum;
    __syncthreads();
    #pragma unroll
    for (int off = 1; off < 1024; off <<= 1) {
        int v = (tid >= off) ? sh[tid - off] : 0;
        __syncthreads();
        sh[tid] += v;
        __syncthreads();
    }
    int run = (tid == 0) ? 0 : sh[tid - 1];

    #pragma unroll
    for (int k = 0; k < CPT; k++) {
        g_start[base + k] = run;
        g_cur[base + k]   = run;
        run += cnt[k];
    }
    __syncthreads();   // make g_start/g_cur visible block-wide

    // packed neighborhood ranges (x-axis +-1, clamped)
    #pragma unroll
    for (int k = 0; k < CPT; k++) {
        const int cell = tid * CPT + k;          // local cell index in structure
        const int x = cell & (G - 1);
        const int lc = (x > 0)     ? cell - 1 : cell;
        const int rc = (x < G - 1) ? cell + 1 : cell;
        const int beg = g_start[s * NCELL + lc];
        const int end = g_start[s * NCELL + rc] + g_cnt[s * NCELL + rc];
        g_nbr[base + k] = make_int2(beg, end);
    }
}

__global__ __launch_bounds__(256) void k_scatter(
    const float* __restrict__ pf, const float* __restrict__ gf,
    const float* __restrict__ pn, const float* __restrict__ gn)
{
    const int t = blockIdx.x * 256 + threadIdx.x;
    int i, s;
    const float* P = map_point(t, pf, gf, pn, gn, &i, &s);
    const float x = P[3 * i], y = P[3 * i + 1], z = P[3 * i + 2];
    const int cell = (cell_coord(z) * G + cell_coord(y)) * G + cell_coord(x);
    const int slot = atomicAdd(&g_cur[s * NCELL + cell], 1);
    const float nh = -0.5f * fmaf(x, x, fmaf(y, y, z * z));
    g_pts[s * CAP + slot] = make_float4(x, y, z, nh);
}

__device__ __forceinline__ float cube_bound(
    float px, float py, float pz, int cx, int cy, int cz, int r)
{
    float b = CUDART_INF_F;
    if (cx - r > 0)     b = fminf(b, px - (-RANGE + (float)(cx - r) * H));
    if (cx + r < G - 1) b = fminf(b, (-RANGE + (float)(cx + r + 1) * H) - px);
    if (cy - r > 0)     b = fminf(b, py - (-RANGE + (float)(cy - r) * H));
    if (cy + r < G - 1) b = fminf(b, (-RANGE + (float)(cy + r + 1) * H) - py);
    if (cz - r > 0)     b = fminf(b, pz - (-RANGE + (float)(cz - r) * H));
    if (cz + r < G - 1) b = fminf(b, (-RANGE + (float)(cz + r + 1) * H) - pz);
    return fmaxf(b * 0.9999f, 0.0f);
}

__global__ __launch_bounds__(QBLK) void k_query()
{
    const int wq   = blockIdx.x * QWARPS + (threadIdx.x >> 5);
    const int lane = threadIdx.x & 31;

    int s_own, u;
    float scale;
    if (wq < 65536) {
        s_own = wq >> 13;
        u     = wq & 8191;
        scale = 0.3f / (4.0f * 8192.0f);
    } else {
        const int tf = wq - 65536;
        s_own = 8 + (tf >> 12);
        u     = tf & 4095;
        scale = 0.7f / (4.0f * 4096.0f);
    }
    const int s = s_own ^ 4;

    const float4 p  = g_pts[s_own * CAP + u];
    const float px = p.x, py = p.y, pz = p.z;
    const float p2 = -2.0f * p.w;
    const int cx = cell_coord(px), cy = cell_coord(py), cz = cell_coord(pz);

    const int*    st  = g_start + s * NCELL;
    const int*    cu  = g_cur   + s * NCELL;
    const int2*   nb  = g_nbr   + s * NCELL;
    const float4* pts = g_pts   + s * CAP;

    float m = -CUDART_INF_F;

    // ---- ring<=1 cube: 9 packed row ranges, scanned as ONE union, MLP=4 ----
    {
        int beg = 0, end = 0;
        if (lane < 9) {
            const int dz = lane / 3 - 1, dy = lane % 3 - 1;
            const int zz = min(max(cz + dz, 0), G - 1);
            const int yy = min(max(cy + dy, 0), G - 1);
            const int2 r2 = nb[(zz * G + yy) * G + cx];
            beg = r2.x;
            end = r2.y;
        }

        int off1, off2, off3, off4, off5, off6, off7, off8, T;
        int dl0, dl1, dl2, dl3, dl4, dl5, dl6, dl7, dl8;
        {
            int o = 0, b, e;
            b = __shfl_sync(0xffffffffu, beg, 0); e = __shfl_sync(0xffffffffu, end, 0);
            dl0 = b - o; o += e - b; off1 = o;
            b = __shfl_sync(0xffffffffu, beg, 1); e = __shfl_sync(0xffffffffu, end, 1);
            dl1 = b - o; o += e - b; off2 = o;
            b = __shfl_sync(0xffffffffu, beg, 2); e = __shfl_sync(0xffffffffu, end, 2);
            dl2 = b - o; o += e - b; off3 = o;
            b = __shfl_sync(0xffffffffu, beg, 3); e = __shfl_sync(0xffffffffu, end, 3);
            dl3 = b - o; o += e - b; off4 = o;
            b = __shfl_sync(0xffffffffu, beg, 4); e = __shfl_sync(0xffffffffu, end, 4);
            dl4 = b - o; o += e - b; off5 = o;
            b = __shfl_sync(0xffffffffu, beg, 5); e = __shfl_sync(0xffffffffu, end, 5);
            dl5 = b - o; o += e - b; off6 = o;
            b = __shfl_sync(0xffffffffu, beg, 6); e = __shfl_sync(0xffffffffu, end, 6);
            dl6 = b - o; o += e - b; off7 = o;
            b = __shfl_sync(0xffffffffu, beg, 7); e = __shfl_sync(0xffffffffu, end, 7);
            dl7 = b - o; o += e - b; off8 = o;
            b = __shfl_sync(0xffffffffu, beg, 8); e = __shfl_sync(0xffffffffu, end, 8);
            dl8 = b - o; o += e - b; T = o;
        }

        // 4 strides per outer iteration; clamp duplicates are harmless (max)
        for (int base = lane; base < T; base += 128) {
            #pragma unroll
            for (int k = 0; k < 4; k++) {
                const int idx = min(base + k * 32, T - 1);
                int d = dl0;
                d = (idx >= off1) ? dl1 : d;
                d = (idx >= off2) ? dl2 : d;
                d = (idx >= off3) ? dl3 : d;
                d = (idx >= off4) ? dl4 : d;
                d = (idx >= off5) ? dl5 : d;
                d = (idx >= off6) ? dl6 : d;
                d = (idx >= off7) ? dl7 : d;
                d = (idx >= off8) ? dl8 : d;
                const float4 q = pts[idx + d];
                m = fmaxf(m, fmaf(px, q.x, fmaf(py, q.y, fmaf(pz, q.z, q.w))));
            }
        }
    }
    #pragma unroll
    for (int o = 16; o; o >>= 1)
        m = fmaxf(m, __shfl_xor_sync(0xffffffffu, m, o));
    float bd2 = fmaf(-2.0f, m, p2);

    // ---- shell expansion (rare): lane-parallel rows ----
    for (int r = 1; r < G - 1; r++) {
        const float bound = cube_bound(px, py, pz, cx, cy, cz, r);
        if (bd2 <= bound * bound) break;

        const int rs = r + 1;
        const int W  = 2 * rs + 1;
        const int NP = W * W;
        float ml = m;
        for (int idx = lane; idx < NP; idx += 32) {
            const int dz = idx / W - rs;
            const int dy = idx - (dz + rs) * W - rs;
            const int zz = cz + dz;
            const int yy = cy + dy;
            if (zz < 0 || zz >= G || yy < 0 || yy >= G) continue;
            const int rb = (zz * G + yy) * G;
            if (dz == -rs || dz == rs || dy == -rs || dy == rs) {
                const int x0 = max(cx - rs, 0), x1 = min(cx + rs, G - 1);
                const int beg = st[rb + x0], end = cu[rb + x1];
                for (int v = beg; v < end; v++) {
                    const float4 q = pts[v];
                    ml = fmaxf(ml, fmaf(px, q.x, fmaf(py, q.y, fmaf(pz, q.z, q.w))));
                }
            } else {
                const int xl = cx - rs;
                if (xl >= 0) {
                    const int beg = st[rb + xl], end = cu[rb + xl];
                    for (int v = beg; v < end; v++) {
                        const float4 q = pts[v];
                        ml = fmaxf(ml, fmaf(px, q.x, fmaf(py, q.y, fmaf(pz, q.z, q.w))));
                    }
                }
                const int xr = cx + rs;
                if (xr < G) {
                    const int beg = st[rb + xr], end = cu[rb + xr];
                    for (int v = beg; v < end; v++) {
                        const float4 q = pts[v];
                        ml = fmaxf(ml, fmaf(px, q.x, fmaf(py, q.y, fmaf(pz, q.z, q.w))));
                    }
                }
            }
        }
        #pragma unroll
        for (int o = 16; o; o >>= 1)
            ml = fmaxf(ml, __shfl_xor_sync(0xffffffffu, ml, o));
        m = ml;
        bd2 = fmaf(-2.0f, m, p2);
    }

    __shared__ float ws[QWARPS];
    if (lane == 0) ws[threadIdx.x >> 5] = bd2 * scale;
    __syncthreads();
    if (threadIdx.x == 0) {
        float v = 0.0f;
        #pragma unroll
        for (int w = 0; w < QWARPS; w++) v += ws[w];
        g_blocksum[blockIdx.x] = v;
    }
}

// final reduce (block 0) + re-zero g_cnt for the next call (all blocks)
__global__ __launch_bounds__(1024) void k_final(float* __restrict__ out) {
    const int tid = threadIdx.x;

    for (int j = blockIdx.x * 1024 + tid; j < NSTRUCT * NCELL; j += FBLK * 1024)
        g_cnt[j] = 0;

    if (blockIdx.x == 0) {
        float v = 0.0f;
        #pragma unroll
        for (int k = 0; k < QBLOCKS / 1024; k++)
            v += g_blocksum[tid + k * 1024];
        #pragma unroll
        for (int o = 16; o; o >>= 1)
            v += __shfl_xor_sync(0xffffffffu, v, o);
        __shared__ float ws[32];
        if ((tid & 31) == 0) ws[tid >> 5] = v;
        __syncthreads();
        if (tid < 32) {
            float x = ws[tid];
            #pragma unroll
            for (int o = 16; o; o >>= 1)
                x += __shfl_xor_sync(0xffffffffu, x, o);
            if (tid == 0) out[0] = x;
        }
    }
}

extern "C" void kernel_launch(void* const* d_in, const int* in_sizes, int n_in,
                              void* d_out, int out_size) {
    const float* pf = (const float*)d_in[0];
    const float* gf = (const float*)d_in[1];
    const float* pn = (const float*)d_in[2];
    const float* gn = (const float*)d_in[3];
    float* out = (float*)d_out;

    // g_cnt is zeroed at module load and re-zeroed by k_final each call.
    k_count<<<NQ_TOTAL / 256, 256>>>(pf, gf, pn, gn);     // launch 0
    k_scan<<<NSTRUCT, 1024>>>();                          // launch 1
    k_scatter<<<NQ_TOTAL / 256, 256>>>(pf, gf, pn, gn);   // launch 2
    k_query<<<QBLOCKS, QBLK>>>();                         // launch 3  (ncu slot)
    k_final<<<FBLK, 1024>>>(out);                         // launch 4
}

// round 10
// speedup vs baseline: 1.1495x; 1.1495x over previous
#include <cuda_runtime.h>
#include <math_constants.h>

// ChamferLoss via exact grid NN. One warp per query.
// Phase A: 2x2x2 nearest-cell window (4 x-rows of 2 cells), flattened into a
//          single union index space (2-level binary segment select).
// Phase B (rare, warp-uniform): full 3x3x3 cube rescan + exact shell expansion.
// d2min(p -> Q) = |p|^2 - 2 * max_j ( p.q_j - 0.5|q_j|^2 )
//
// 16 structures: s in [0,8) nonfiltered (0-3 pn, 4-7 gn, 8192 pts),
//                s in [8,16) filtered (8-11 pf, 12-15 gf, 4096 pts).
// Structure s queries partner s^4.
//
// Exactness: any unscanned point differs by >= 1 cell index beyond a scanned
// face; margins are exact per-axis distances to window/cube faces (infinite
// on domain-clamped sides, since edge cells catch all clamped coordinates).
// Rescans are harmless: max is idempotent.

#define G     32
#define NCELL (G * G * G)
#define H     0.32f
#define INVH  3.125f
#define RANGE 5.12f
#define NSTRUCT 16
#define CAP   8192

#define NQ_TOTAL 98304
#define QWARPS   4
#define QBLK     (QWARPS * 32)
#define QBLOCKS  (NQ_TOTAL / QWARPS)

__device__ int    g_cnt  [NSTRUCT * NCELL];   // zero at load; re-zeroed by k_scan
__device__ int    g_start[NSTRUCT * NCELL];
__device__ int    g_cur  [NSTRUCT * NCELL];   // after scatter: end of each cell
__device__ float4 g_pts  [NSTRUCT * CAP];

__device__ __forceinline__ int cell_coord(float x) {
    int c = (int)floorf((x + RANGE) * INVH);
    return min(max(c, 0), G - 1);
}

__device__ __forceinline__ const float* map_point(
    int t, const float* pf, const float* gf, const float* pn, const float* gn,
    int* idx, int* s)
{
    if (t < 65536) {
        const int grp = t >> 13;
        *idx = t & 8191;
        *s   = grp;
        return ((grp < 4) ? pn : gn) + (size_t)(grp & 3) * 8192 * 3;
    } else {
        const int tf  = t - 65536;
        const int grp = tf >> 12;
        *idx = tf & 4095;
        *s   = 8 + grp;
        return ((grp < 4) ? pf : gf) + (size_t)(grp & 3) * 4096 * 3;
    }
}

__global__ __launch_bounds__(256) void k_count(
    const float* __restrict__ pf, const float* __restrict__ gf,
    const float* __restrict__ pn, const float* __restrict__ gn)
{
    const int t = blockIdx.x * 256 + threadIdx.x;
    int i, s;
    const float* P = map_point(t, pf, gf, pn, gn, &i, &s);
    const float x = P[3 * i], y = P[3 * i + 1], z = P[3 * i + 2];
    const int cell = (cell_coord(z) * G + cell_coord(y)) * G + cell_coord(x);
    atomicAdd(&g_cnt[s * NCELL + cell], 1);
}

// prefix scan per structure (shuffle-based, 2 barriers); zeroes g_cnt + out
__global__ __launch_bounds__(1024) void k_scan(float* __restrict__ out) {
    const int s    = blockIdx.x;
    const int tid  = threadIdx.x;
    const int lane = tid & 31;
    const int wid  = tid >> 5;
    const int CPT  = NCELL / 1024;          // 32 cells per thread
    const int base = s * NCELL + tid * CPT;

    if (s == 0 && tid == 0) out[0] = 0.0f;

    int sum = 0;
    #pragma unroll
    for (int k = 0; k < CPT; k++) sum += g_cnt[base + k];

    // warp inclusive scan
    int v = sum;
    #pragma unroll
    for (int o = 1; o < 32; o <<= 1) {
        const int t2 = __shfl_up_sync(0xffffffffu, v, o);
        if (lane >= o) v += t2;
    }

    __shared__ int sh[32];
    if (lane == 31) sh[wid] = v;
    __syncthreads();
    if (wid == 0) {
        int w = sh[lane];
        #pragma unroll
        for (int o = 1; o < 32; o <<= 1) {
            const int t2 = __shfl_up_sync(0xffffffffu, w, o);
            if (lane >= o) w += t2;
        }
        sh[lane] = w;
    }
    __syncthreads();

    int run = (v - sum) + ((wid > 0) ? sh[wid - 1] : 0);   // exclusive prefix

    #pragma unroll
    for (int k = 0; k < CPT; k++) {
        const int c = g_cnt[base + k];
        g_start[base + k] = run;
        g_cur[base + k]   = run;
        g_cnt[base + k]   = 0;               // ready for next call
        run += c;
    }
}

__global__ __launch_bounds__(256) void k_scatter(
    const float* __restrict__ pf, const float* __restrict__ gf,
    const float* __restrict__ pn, const float* __restrict__ gn)
{
    const int t = blockIdx.x * 256 + threadIdx.x;
    int i, s;
    const float* P = map_point(t, pf, gf, pn, gn, &i, &s);
    const float x = P[3 * i], y = P[3 * i + 1], z = P[3 * i + 2];
    const int cell = (cell_coord(z) * G + cell_coord(y)) * G + cell_coord(x);
    const int slot = atomicAdd(&g_cur[s * NCELL + cell], 1);
    const float nh = -0.5f * fmaf(x, x, fmaf(y, y, z * z));
    g_pts[s * CAP + slot] = make_float4(x, y, z, nh);
}

__device__ __forceinline__ float cube_bound(
    float px, float py, float pz, int cx, int cy, int cz, int r)
{
    float b = CUDART_INF_F;
    if (cx - r > 0)     b = fminf(b, px - (-RANGE + (float)(cx - r) * H));
    if (cx + r < G - 1) b = fminf(b, (-RANGE + (float)(cx + r + 1) * H) - px);
    if (cy - r > 0)     b = fminf(b, py - (-RANGE + (float)(cy - r) * H));
    if (cy + r < G - 1) b = fminf(b, (-RANGE + (float)(cy + r + 1) * H) - py);
    if (cz - r > 0)     b = fminf(b, pz - (-RANGE + (float)(cz - r) * H));
    if (cz + r < G - 1) b = fminf(b, (-RANGE + (float)(cz + r + 1) * H) - pz);
    return fmaxf(b * 0.9999f, 0.0f);
}

__global__ __launch_bounds__(QBLK) void k_query(float* __restrict__ out)
{
    const int wq   = blockIdx.x * QWARPS + (threadIdx.x >> 5);
    const int lane = threadIdx.x & 31;

    int s_own, u;
    float scale;
    if (wq < 65536) {
        s_own = wq >> 13;
        u     = wq & 8191;
        scale = 0.3f / (4.0f * 8192.0f);
    } else {
        const int tf = wq - 65536;
        s_own = 8 + (tf >> 12);
        u     = tf & 4095;
        scale = 0.7f / (4.0f * 4096.0f);
    }
    const int s = s_own ^ 4;

    const float4 p  = g_pts[s_own * CAP + u];
    const float px = p.x, py = p.y, pz = p.z;
    const float p2 = -2.0f * p.w;

    // cell + nearest-window selection per axis
    const float rx = (px + RANGE) * INVH;
    const float ry = (py + RANGE) * INVH;
    const float rz = (pz + RANGE) * INVH;
    const float fx = floorf(rx), fy = floorf(ry), fz = floorf(rz);
    const int cx = min(max((int)fx, 0), G - 1);
    const int cy = min(max((int)fy, 0), G - 1);
    const int cz = min(max((int)fz, 0), G - 1);
    const int lox = min(max((rx - fx >= 0.5f) ? cx : cx - 1, 0), G - 2);
    const int loy = min(max((ry - fy >= 0.5f) ? cy : cy - 1, 0), G - 2);
    const int loz = min(max((rz - fz >= 0.5f) ? cz : cz - 1, 0), G - 2);

    const int*    st  = g_start + s * NCELL;
    const int*    cu  = g_cur   + s * NCELL;
    const float4* pts = g_pts   + s * CAP;

    float m = -CUDART_INF_F;

    // ---- Phase A: 2x2x2 window = 4 x-rows of 2 cells, union scan ----
    {
        int rv = 0;
        if (lane < 8) {
            const int k  = lane & 3;
            const int rb = ((loz + (k >> 1)) * G + (loy + (k & 1))) * G;
            rv = (lane < 4) ? st[rb + lox] : cu[rb + lox + 1];
        }
        int off1, off2, off3, T;
        int dl0, dl1, dl2, dl3;
        {
            int o = 0, b, e;
            b = __shfl_sync(0xffffffffu, rv, 0); e = __shfl_sync(0xffffffffu, rv, 4);
            dl0 = b - o; o += e - b; off1 = o;
            b = __shfl_sync(0xffffffffu, rv, 1); e = __shfl_sync(0xffffffffu, rv, 5);
            dl1 = b - o; o += e - b; off2 = o;
            b = __shfl_sync(0xffffffffu, rv, 2); e = __shfl_sync(0xffffffffu, rv, 6);
            dl2 = b - o; o += e - b; off3 = o;
            b = __shfl_sync(0xffffffffu, rv, 3); e = __shfl_sync(0xffffffffu, rv, 7);
            dl3 = b - o; o += e - b; T = o;
        }

        int idx = lane;
        for (; idx + 32 < T; idx += 64) {
            {
                const int d = (idx < off2) ? ((idx < off1) ? dl0 : dl1)
                                           : ((idx < off3) ? dl2 : dl3);
                const float4 q = pts[idx + d];
                m = fmaxf(m, fmaf(px, q.x, fmaf(py, q.y, fmaf(pz, q.z, q.w))));
            }
            {
                const int j = idx + 32;
                const int d = (j < off2) ? ((j < off1) ? dl0 : dl1)
                                         : ((j < off3) ? dl2 : dl3);
                const float4 q = pts[j + d];
                m = fmaxf(m, fmaf(px, q.x, fmaf(py, q.y, fmaf(pz, q.z, q.w))));
            }
        }
        if (idx < T) {
            const int d = (idx < off2) ? ((idx < off1) ? dl0 : dl1)
                                       : ((idx < off3) ? dl2 : dl3);
            const float4 q = pts[idx + d];
            m = fmaxf(m, fmaf(px, q.x, fmaf(py, q.y, fmaf(pz, q.z, q.w))));
        }
    }
    #pragma unroll
    for (int o = 16; o; o >>= 1)
        m = fmaxf(m, __shfl_xor_sync(0xffffffffu, m, o));
    float bd2 = fmaf(-2.0f, m, p2);

    // exact margin to window faces (inf on domain-clamped sides)
    float b1 = CUDART_INF_F;
    if (lox > 0)         b1 = fminf(b1, px - (-RANGE + (float)lox * H));
    if (lox + 1 < G - 1) b1 = fminf(b1, (-RANGE + (float)(lox + 2) * H) - px);
    if (loy > 0)         b1 = fminf(b1, py - (-RANGE + (float)loy * H));
    if (loy + 1 < G - 1) b1 = fminf(b1, (-RANGE + (float)(loy + 2) * H) - py);
    if (loz > 0)         b1 = fminf(b1, pz - (-RANGE + (float)loz * H));
    if (loz + 1 < G - 1) b1 = fminf(b1, (-RANGE + (float)(loz + 2) * H) - pz);
    b1 = fmaxf(b1 * 0.9999f, 0.0f);

    if (bd2 > b1 * b1) {
        // ---- Phase B: full 3x3x3 cube rescan (warp loop per row) ----
        const int x0 = max(cx - 1, 0), x1 = min(cx + 1, G - 1);
        int beg = 0, end = 0;
        if (lane < 9) {
            const int zz = min(max(cz + lane / 3 - 1, 0), G - 1);
            const int yy = min(max(cy + lane % 3 - 1, 0), G - 1);
            const int rb = (zz * G + yy) * G;
            beg = st[rb + x0];
            end = cu[rb + x1];
        }
        float ml = m;
        #pragma unroll
        for (int k = 0; k < 9; k++) {
            const int b = __shfl_sync(0xffffffffu, beg, k);
            const int e = __shfl_sync(0xffffffffu, end, k);
            for (int v = b + lane; v < e; v += 32) {
                const float4 q = pts[v];
                ml = fmaxf(ml, fmaf(px, q.x, fmaf(py, q.y, fmaf(pz, q.z, q.w))));
            }
        }
        #pragma unroll
        for (int o = 16; o; o >>= 1)
            ml = fmaxf(ml, __shfl_xor_sync(0xffffffffu, ml, o));
        m = ml;
        bd2 = fmaf(-2.0f, m, p2);

        // ---- exact shell expansion ----
        for (int r = 1; r < G - 1; r++) {
            const float bound = cube_bound(px, py, pz, cx, cy, cz, r);
            if (bd2 <= bound * bound) break;

            const int rs = r + 1;
            const int W  = 2 * rs + 1;
            const int NP = W * W;
            float m2 = m;
            for (int idx = lane; idx < NP; idx += 32) {
                const int dz = idx / W - rs;
                const int dy = idx - (dz + rs) * W - rs;
                const int zz = cz + dz;
                const int yy = cy + dy;
                if (zz < 0 || zz >= G || yy < 0 || yy >= G) continue;
                const int rb = (zz * G + yy) * G;
                if (dz == -rs || dz == rs || dy == -rs || dy == rs) {
                    const int xb = max(cx - rs, 0), xe = min(cx + rs, G - 1);
                    const int bb = st[rb + xb], ee = cu[rb + xe];
                    for (int v = bb; v < ee; v++) {
                        const float4 q = pts[v];
                        m2 = fmaxf(m2, fmaf(px, q.x, fmaf(py, q.y, fmaf(pz, q.z, q.w))));
                    }
                } else {
                    const int xl = cx - rs;
                    if (xl >= 0) {
                        const int bb = st[rb + xl], ee = cu[rb + xl];
                        for (int v = bb; v < ee; v++) {
                            const float4 q = pts[v];
                            m2 = fmaxf(m2, fmaf(px, q.x, fmaf(py, q.y, fmaf(pz, q.z, q.w))));
                        }
                    }
                    const int xr = cx + rs;
                    if (xr < G) {
                        const int bb = st[rb + xr], ee = cu[rb + xr];
                        for (int v = bb; v < ee; v++) {
                            const float4 q = pts[v];
                            m2 = fmaxf(m2, fmaf(px, q.x, fmaf(py, q.y, fmaf(pz, q.z, q.w))));
                        }
                    }
                }
            }
            #pragma unroll
            for (int o = 16; o; o >>= 1)
                m2 = fmaxf(m2, __shfl_xor_sync(0xffffffffu, m2, o));
            m = m2;
            bd2 = fmaf(-2.0f, m, p2);
        }
    }

    // block reduction of QWARPS per-warp values + one atomic per block
    __shared__ float ws[QWARPS];
    if (lane == 0) ws[threadIdx.x >> 5] = bd2 * scale;
    __syncthreads();
    if (threadIdx.x == 0) {
        float v = 0.0f;
        #pragma unroll
        for (int w = 0; w < QWARPS; w++) v += ws[w];
        atomicAdd(out, v);
    }
}

extern "C" void kernel_launch(void* const* d_in, const int* in_sizes, int n_in,
                              void* d_out, int out_size) {
    const float* pf = (const float*)d_in[0];
    const float* gf = (const float*)d_in[1];
    const float* pn = (const float*)d_in[2];
    const float* gn = (const float*)d_in[3];
    float* out = (float*)d_out;

    // g_cnt zeroed at module load and re-zeroed by k_scan every call.
    k_count<<<NQ_TOTAL / 256, 256>>>(pf, gf, pn, gn);     // launch 0
    k_scan<<<NSTRUCT, 1024>>>(out);                       // launch 1
    k_scatter<<<NQ_TOTAL / 256, 256>>>(pf, gf, pn, gn);   // launch 2
    k_query<<<QBLOCKS, QBLK>>>(out);                      // launch 3 (ncu slot)
}

// round 12
// speedup vs baseline: 2.2861x; 1.9888x over previous
#include <cuda_runtime.h>
#include <math_constants.h>

// ChamferLoss via exact grid NN. One warp per query.
// Phase A: 2x2x2 nearest-cell window (4 x-rows of 2 cells), union scan with
//          warp-scan offset construction (short dependency chain).
// Phase B (rare, warp-uniform): full 3x3x3 rescan + exact shell expansion.
// k_scan is fully coalesced (warp-chunked cells, nL=1 accesses).
// d2min(p -> Q) = |p|^2 - 2 * max_j ( p.q_j - 0.5|q_j|^2 )
//
// 16 structures: s in [0,8) nonfiltered (0-3 pn, 4-7 gn, 8192 pts),
//                s in [8,16) filtered (8-11 pf, 12-15 gf, 4096 pts).
// Structure s queries partner s^4.
//
// Exactness: any unscanned point differs by >= 1 cell index beyond a scanned
// face; margins are exact per-axis distances to window/cube faces (infinite
// on domain-clamped sides). Rescans are harmless: max is idempotent.

#define G     32
#define NCELL (G * G * G)
#define H     0.32f
#define INVH  3.125f
#define RANGE 5.12f
#define NSTRUCT 16
#define CAP   8192

#define NQ_TOTAL 98304
#define QWARPS   8
#define QBLK     (QWARPS * 32)
#define QBLOCKS  (NQ_TOTAL / QWARPS)    // one WARP per query: 12288 blocks

__device__ int    g_cnt  [NSTRUCT * NCELL];   // zero at load; re-zeroed by k_scan
__device__ int    g_start[NSTRUCT * NCELL];
__device__ int    g_cur  [NSTRUCT * NCELL];   // after scatter: end of each cell
__device__ float4 g_pts  [NSTRUCT * CAP];

__device__ __forceinline__ int cell_coord(float x) {
    int c = (int)floorf((x + RANGE) * INVH);
    return min(max(c, 0), G - 1);
}

__device__ __forceinline__ const float* map_point(
    int t, const float* pf, const float* gf, const float* pn, const float* gn,
    int* idx, int* s)
{
    if (t < 65536) {
        const int grp = t >> 13;
        *idx = t & 8191;
        *s   = grp;
        return ((grp < 4) ? pn : gn) + (size_t)(grp & 3) * 8192 * 3;
    } else {
        const int tf  = t - 65536;
        const int grp = tf >> 12;
        *idx = tf & 4095;
        *s   = 8 + grp;
        return ((grp < 4) ? pf : gf) + (size_t)(grp & 3) * 4096 * 3;
    }
}

__global__ __launch_bounds__(256) void k_count(
    const float* __restrict__ pf, const float* __restrict__ gf,
    const float* __restrict__ pn, const float* __restrict__ gn)
{
    const int t = blockIdx.x * 256 + threadIdx.x;
    int i, s;
    const float* P = map_point(t, pf, gf, pn, gn, &i, &s);
    const float x = P[3 * i], y = P[3 * i + 1], z = P[3 * i + 2];
    const int cell = (cell_coord(z) * G + cell_coord(y)) * G + cell_coord(x);
    atomicAdd(&g_cnt[s * NCELL + cell], 1);
}

// Coalesced prefix scan per structure. Warp w owns cells [w*1024, w*1024+1024),
// accessed as k*32 + lane (nL=1). Counts cached in registers. Zeroes g_cnt+out.
__global__ __launch_bounds__(1024) void k_scan(float* __restrict__ out) {
    const int s    = blockIdx.x;
    const int tid  = threadIdx.x;
    const int lane = tid & 31;
    const int wid  = tid >> 5;
    const int gbase = s * NCELL + wid * 1024;

    if (s == 0 && tid == 0) out[0] = 0.0f;

    int cnt[32];
    int lane_total = 0;
    #pragma unroll
    for (int k = 0; k < 32; k++) {
        cnt[k] = g_cnt[gbase + k * 32 + lane];
        lane_total += cnt[k];
    }

    // warp total
    int wt = lane_total;
    #pragma unroll
    for (int o = 16; o; o >>= 1) wt += __shfl_xor_sync(0xffffffffu, wt, o);

    __shared__ int sh[32];
    if (lane == 0) sh[wid] = wt;
    __syncthreads();
    if (wid == 0) {
        int v = sh[lane];
        int incl = v;
        #pragma unroll
        for (int o = 1; o < 32; o <<= 1) {
            const int t2 = __shfl_up_sync(0xffffffffu, incl, o);
            if (lane >= o) incl += t2;
        }
        sh[lane] = incl - v;    // exclusive warp base
    }
    __syncthreads();

    int run = sh[wid];
    #pragma unroll
    for (int k = 0; k < 32; k++) {
        const int c = cnt[k];
        int incl = c;
        #pragma unroll
        for (int o = 1; o < 32; o <<= 1) {
            const int t2 = __shfl_up_sync(0xffffffffu, incl, o);
            if (lane >= o) incl += t2;
        }
        const int idx = gbase + k * 32 + lane;
        const int stv = run + incl - c;
        g_start[idx] = stv;
        g_cur[idx]   = stv;
        g_cnt[idx]   = 0;
        run += __shfl_sync(0xffffffffu, incl, 31);
    }
}

__global__ __launch_bounds__(256) void k_scatter(
    const float* __restrict__ pf, const float* __restrict__ gf,
    const float* __restrict__ pn, const float* __restrict__ gn)
{
    const int t = blockIdx.x * 256 + threadIdx.x;
    int i, s;
    const float* P = map_point(t, pf, gf, pn, gn, &i, &s);
    const float x = P[3 * i], y = P[3 * i + 1], z = P[3 * i + 2];
    const int cell = (cell_coord(z) * G + cell_coord(y)) * G + cell_coord(x);
    const int slot = atomicAdd(&g_cur[s * NCELL + cell], 1);
    const float nh = -0.5f * fmaf(x, x, fmaf(y, y, z * z));
    g_pts[s * CAP + slot] = make_float4(x, y, z, nh);
}

__device__ __forceinline__ float cube_bound(
    float px, float py, float pz, int cx, int cy, int cz, int r)
{
    float b = CUDART_INF_F;
    if (cx - r > 0)     b = fminf(b, px - (-RANGE + (float)(cx - r) * H));
    if (cx + r < G - 1) b = fminf(b, (-RANGE + (float)(cx + r + 1) * H) - px);
    if (cy - r > 0)     b = fminf(b, py - (-RANGE + (float)(cy - r) * H));
    if (cy + r < G - 1) b = fminf(b, (-RANGE + (float)(cy + r + 1) * H) - py);
    if (cz - r > 0)     b = fminf(b, pz - (-RANGE + (float)(cz - r) * H));
    if (cz + r < G - 1) b = fminf(b, (-RANGE + (float)(cz + r + 1) * H) - pz);
    return fmaxf(b * 0.9999f, 0.0f);
}

__global__ __launch_bounds__(QBLK) void k_query(float* __restrict__ out)
{
    const int wq   = blockIdx.x * QWARPS + (threadIdx.x >> 5);
    const int lane = threadIdx.x & 31;

    int s_own, u;
    float scale;
    if (wq < 65536) {
        s_own = wq >> 13;
        u     = wq & 8191;
        scale = 0.3f / (4.0f * 8192.0f);
    } else {
        const int tf = wq - 65536;
        s_own = 8 + (tf >> 12);
        u     = tf & 4095;
        scale = 0.7f / (4.0f * 4096.0f);
    }
    const int s = s_own ^ 4;

    const float4 p  = g_pts[s_own * CAP + u];
    const float px = p.x, py = p.y, pz = p.z;
    const float p2 = -2.0f * p.w;

    const float rx = (px + RANGE) * INVH;
    const float ry = (py + RANGE) * INVH;
    const float rz = (pz + RANGE) * INVH;
    const float fx = floorf(rx), fy = floorf(ry), fz = floorf(rz);
    const int cx = min(max((int)fx, 0), G - 1);
    const int cy = min(max((int)fy, 0), G - 1);
    const int cz = min(max((int)fz, 0), G - 1);
    const int lox = min(max((rx - fx >= 0.5f) ? cx : cx - 1, 0), G - 2);
    const int loy = min(max((ry - fy >= 0.5f) ? cy : cy - 1, 0), G - 2);
    const int loz = min(max((rz - fz >= 0.5f) ? cz : cz - 1, 0), G - 2);

    const int*    st  = g_start + s * NCELL;
    const int*    cu  = g_cur   + s * NCELL;
    const float4* pts = g_pts   + s * CAP;

    float m = -CUDART_INF_F;

    // ---- Phase A: 2x2x2 window, union scan; offsets via 4-lane warp scan ----
    {
        int rv = 0;
        if (lane < 8) {
            const int k  = lane & 3;
            const int rb = ((loz + (k >> 1)) * G + (loy + (k & 1))) * G;
            rv = (lane < 4) ? st[rb + lox] : cu[rb + lox + 1];
        }
        // lanes 0-3: cnt_k = end_k - beg_k
        const int endv = __shfl_down_sync(0xffffffffu, rv, 4);
        int cnt = endv - rv;                       // valid on lanes 0-3
        int incl = cnt;
        {
            int t2 = __shfl_up_sync(0xffffffffu, incl, 1);
            if (lane >= 1) incl += t2;
            t2 = __shfl_up_sync(0xffffffffu, incl, 2);
            if (lane >= 2) incl += t2;
        }
        const int dl = rv - (incl - cnt);          // beg_k - excl_k, lanes 0-3

        const int off1 = __shfl_sync(0xffffffffu, incl, 0);
        const int off2 = __shfl_sync(0xffffffffu, incl, 1);
        const int off3 = __shfl_sync(0xffffffffu, incl, 2);
        const int T    = __shfl_sync(0xffffffffu, incl, 3);
        const int dl0  = __shfl_sync(0xffffffffu, dl, 0);
        const int dl1  = __shfl_sync(0xffffffffu, dl, 1);
        const int dl2  = __shfl_sync(0xffffffffu, dl, 2);
        const int dl3  = __shfl_sync(0xffffffffu, dl, 3);

        int idx = lane;
        for (; idx + 32 < T; idx += 64) {
            {
                const int d = (idx < off2) ? ((idx < off1) ? dl0 : dl1)
                                           : ((idx < off3) ? dl2 : dl3);
                const float4 q = pts[idx + d];
                m = fmaxf(m, fmaf(px, q.x, fmaf(py, q.y, fmaf(pz, q.z, q.w))));
            }
            {
                const int j = idx + 32;
                const int d = (j < off2) ? ((j < off1) ? dl0 : dl1)
                                         : ((j < off3) ? dl2 : dl3);
                const float4 q = pts[j + d];
                m = fmaxf(m, fmaf(px, q.x, fmaf(py, q.y, fmaf(pz, q.z, q.w))));
            }
        }
        if (idx < T) {
            const int d = (idx < off2) ? ((idx < off1) ? dl0 : dl1)
                                       : ((idx < off3) ? dl2 : dl3);
            const float4 q = pts[idx + d];
            m = fmaxf(m, fmaf(px, q.x, fmaf(py, q.y, fmaf(pz, q.z, q.w))));
        }
    }
    #pragma unroll
    for (int o = 16; o; o >>= 1)
        m = fmaxf(m, __shfl_xor_sync(0xffffffffu, m, o));
    float bd2 = fmaf(-2.0f, m, p2);

    // exact margin to window faces (inf on domain-clamped sides)
    float b1 = CUDART_INF_F;
    if (lox > 0)         b1 = fminf(b1, px - (-RANGE + (float)lox * H));
    if (lox + 1 < G - 1) b1 = fminf(b1, (-RANGE + (float)(lox + 2) * H) - px);
    if (loy > 0)         b1 = fminf(b1, py - (-RANGE + (float)loy * H));
    if (loy + 1 < G - 1) b1 = fminf(b1, (-RANGE + (float)(loy + 2) * H) - py);
    if (loz > 0)         b1 = fminf(b1, pz - (-RANGE + (float)loz * H));
    if (loz + 1 < G - 1) b1 = fminf(b1, (-RANGE + (float)(loz + 2) * H) - pz);
    b1 = fmaxf(b1 * 0.9999f, 0.0f);

    if (bd2 > b1 * b1) {
        // ---- Phase B: full 3x3x3 cube rescan ----
        const int x0 = max(cx - 1, 0), x1 = min(cx + 1, G - 1);
        int beg = 0, end = 0;
        if (lane < 9) {
            const int zz = min(max(cz + lane / 3 - 1, 0), G - 1);
            const int yy = min(max(cy + lane % 3 - 1, 0), G - 1);
            const int rb = (zz * G + yy) * G;
            beg = st[rb + x0];
            end = cu[rb + x1];
        }
        float ml = m;
        #pragma unroll
        for (int k = 0; k < 9; k++) {
            const int b = __shfl_sync(0xffffffffu, beg, k);
            const int e = __shfl_sync(0xffffffffu, end, k);
            for (int v = b + lane; v < e; v += 32) {
                const float4 q = pts[v];
                ml = fmaxf(ml, fmaf(px, q.x, fmaf(py, q.y, fmaf(pz, q.z, q.w))));
            }
        }
        #pragma unroll
        for (int o = 16; o; o >>= 1)
            ml = fmaxf(ml, __shfl_xor_sync(0xffffffffu, ml, o));
        m = ml;
        bd2 = fmaf(-2.0f, m, p2);

        // ---- exact shell expansion ----
        for (int r = 1; r < G - 1; r++) {
            const float bound = cube_bound(px, py, pz, cx, cy, cz, r);
            if (bd2 <= bound * bound) break;

            const int rs = r + 1;
            const int W  = 2 * rs + 1;
            const int NP = W * W;
            float m2 = m;
            for (int idx = lane; idx < NP; idx += 32) {
                const int dz = idx / W - rs;
                const int dy = idx - (dz + rs) * W - rs;
                const int zz = cz + dz;
                const int yy = cy + dy;
                if (zz < 0 || zz >= G || yy < 0 || yy >= G) continue;
                const int rb = (zz * G + yy) * G;
                if (dz == -rs || dz == rs || dy == -rs || dy == rs) {
                    const int xb = max(cx - rs, 0), xe = min(cx + rs, G - 1);
                    const int bb = st[rb + xb], ee = cu[rb + xe];
                    for (int v = bb; v < ee; v++) {
                        const float4 q = pts[v];
                        m2 = fmaxf(m2, fmaf(px, q.x, fmaf(py, q.y, fmaf(pz, q.z, q.w))));
                    }
                } else {
                    const int xl = cx - rs;
                    if (xl >= 0) {
                        const int bb = st[rb + xl], ee = cu[rb + xl];
                        for (int v = bb; v < ee; v++) {
                            const float4 q = pts[v];
                            m2 = fmaxf(m2, fmaf(px, q.x, fmaf(py, q.y, fmaf(pz, q.z, q.w))));
                        }
                    }
                    const int xr = cx + rs;
                    if (xr < G) {
                        const int bb = st[rb + xr], ee = cu[rb + xr];
                        for (int v = bb; v < ee; v++) {
                            const float4 q = pts[v];
                            m2 = fmaxf(m2, fmaf(px, q.x, fmaf(py, q.y, fmaf(pz, q.z, q.w))));
                        }
                    }
                }
            }
            #pragma unroll
            for (int o = 16; o; o >>= 1)
                m2 = fmaxf(m2, __shfl_xor_sync(0xffffffffu, m2, o));
            m = m2;
            bd2 = fmaf(-2.0f, m, p2);
        }
    }

    // block reduction of QWARPS per-warp values + one atomic per block
    __shared__ float ws[QWARPS];
    if (lane == 0) ws[threadIdx.x >> 5] = bd2 * scale;
    __syncthreads();
    if (threadIdx.x == 0) {
        float v = 0.0f;
        #pragma unroll
        for (int w = 0; w < QWARPS; w++) v += ws[w];
        atomicAdd(out, v);
    }
}

extern "C" void kernel_launch(void* const* d_in, const int* in_sizes, int n_in,
                              void* d_out, int out_size) {
    const float* pf = (const float*)d_in[0];
    const float* gf = (const float*)d_in[1];
    const float* pn = (const float*)d_in[2];
    const float* gn = (const float*)d_in[3];
    float* out = (float*)d_out;

    // g_cnt zeroed at module load and re-zeroed by k_scan every call.
    k_count<<<NQ_TOTAL / 256, 256>>>(pf, gf, pn, gn);     // launch 0
    k_scan<<<NSTRUCT, 1024>>>(out);                       // launch 1
    k_scatter<<<NQ_TOTAL / 256, 256>>>(pf, gf, pn, gn);   // launch 2
    k_query<<<QBLOCKS, QBLK>>>(out);                      // launch 3 (ncu slot)
}

// round 13
// speedup vs baseline: 2.8175x; 1.2325x over previous
#include <cuda_runtime.h>
#include <math_constants.h>

// ChamferLoss via exact grid NN. FOUR queries per warp (8 lanes each):
// the 2x2x2 window's 8 range words load in ONE warp instruction for 4
// queries; offset scan / max-reduce run at width 8. Phase B (rare) is
// warp-wide per flagged query via ballot loop.
// d2min(p -> Q) = |p|^2 - 2 * max_j ( p.q_j - 0.5|q_j|^2 )
//
// 16 structures: s in [0,8) nonfiltered (0-3 pn, 4-7 gn, 8192 pts),
//                s in [8,16) filtered (8-11 pf, 12-15 gf, 4096 pts).
// Structure s queries partner s^4.
//
// Exactness: any unscanned point differs by >= 1 cell index beyond a scanned
// face; margins are exact per-axis distances to window/cube faces (infinite
// on domain-clamped sides). Rescans are harmless: max is idempotent.

#define G     32
#define NCELL (G * G * G)
#define H     0.32f
#define INVH  3.125f
#define RANGE 5.12f
#define NSTRUCT 16
#define CAP   8192

#define NQ_TOTAL 98304
#define QWARPS   8
#define QBLK     (QWARPS * 32)
#define QPB      (QWARPS * 4)            // 32 queries per block
#define QBLOCKS  (NQ_TOTAL / QPB)        // 3072 blocks

#define FULL 0xffffffffu

__device__ int    g_cnt  [NSTRUCT * NCELL];   // zero at load; re-zeroed by k_scan
__device__ int    g_start[NSTRUCT * NCELL];
__device__ int    g_cur  [NSTRUCT * NCELL];   // after scatter: end of each cell
__device__ float4 g_pts  [NSTRUCT * CAP];

__device__ __forceinline__ int cell_coord(float x) {
    int c = (int)floorf((x + RANGE) * INVH);
    return min(max(c, 0), G - 1);
}

__device__ __forceinline__ const float* map_point(
    int t, const float* pf, const float* gf, const float* pn, const float* gn,
    int* idx, int* s)
{
    if (t < 65536) {
        const int grp = t >> 13;
        *idx = t & 8191;
        *s   = grp;
        return ((grp < 4) ? pn : gn) + (size_t)(grp & 3) * 8192 * 3;
    } else {
        const int tf  = t - 65536;
        const int grp = tf >> 12;
        *idx = tf & 4095;
        *s   = 8 + grp;
        return ((grp < 4) ? pf : gf) + (size_t)(grp & 3) * 4096 * 3;
    }
}

__global__ __launch_bounds__(256) void k_count(
    const float* __restrict__ pf, const float* __restrict__ gf,
    const float* __restrict__ pn, const float* __restrict__ gn)
{
    const int t = blockIdx.x * 256 + threadIdx.x;
    int i, s;
    const float* P = map_point(t, pf, gf, pn, gn, &i, &s);
    const float x = P[3 * i], y = P[3 * i + 1], z = P[3 * i + 2];
    const int cell = (cell_coord(z) * G + cell_coord(y)) * G + cell_coord(x);
    atomicAdd(&g_cnt[s * NCELL + cell], 1);
}

// Coalesced prefix scan per structure (warp-chunked, nL=1). Zeroes g_cnt+out.
__global__ __launch_bounds__(1024) void k_scan(float* __restrict__ out) {
    const int s    = blockIdx.x;
    const int tid  = threadIdx.x;
    const int lane = tid & 31;
    const int wid  = tid >> 5;
    const int gbase = s * NCELL + wid * 1024;

    if (s == 0 && tid == 0) out[0] = 0.0f;

    int cnt[32];
    int lane_total = 0;
    #pragma unroll
    for (int k = 0; k < 32; k++) {
        cnt[k] = g_cnt[gbase + k * 32 + lane];
        lane_total += cnt[k];
    }

    int wt = lane_total;
    #pragma unroll
    for (int o = 16; o; o >>= 1) wt += __shfl_xor_sync(FULL, wt, o);

    __shared__ int sh[32];
    if (lane == 0) sh[wid] = wt;
    __syncthreads();
    if (wid == 0) {
        int v = sh[lane];
        int incl = v;
        #pragma unroll
        for (int o = 1; o < 32; o <<= 1) {
            const int t2 = __shfl_up_sync(FULL, incl, o);
            if (lane >= o) incl += t2;
        }
        sh[lane] = incl - v;
    }
    __syncthreads();

    int run = sh[wid];
    #pragma unroll
    for (int k = 0; k < 32; k++) {
        const int c = cnt[k];
        int incl = c;
        #pragma unroll
        for (int o = 1; o < 32; o <<= 1) {
            const int t2 = __shfl_up_sync(FULL, incl, o);
            if (lane >= o) incl += t2;
        }
        const int idx = gbase + k * 32 + lane;
        const int stv = run + incl - c;
        g_start[idx] = stv;
        g_cur[idx]   = stv;
        g_cnt[idx]   = 0;
        run += __shfl_sync(FULL, incl, 31);
    }
}

__global__ __launch_bounds__(256) void k_scatter(
    const float* __restrict__ pf, const float* __restrict__ gf,
    const float* __restrict__ pn, const float* __restrict__ gn)
{
    const int t = blockIdx.x * 256 + threadIdx.x;
    int i, s;
    const float* P = map_point(t, pf, gf, pn, gn, &i, &s);
    const float x = P[3 * i], y = P[3 * i + 1], z = P[3 * i + 2];
    const int cell = (cell_coord(z) * G + cell_coord(y)) * G + cell_coord(x);
    const int slot = atomicAdd(&g_cur[s * NCELL + cell], 1);
    const float nh = -0.5f * fmaf(x, x, fmaf(y, y, z * z));
    g_pts[s * CAP + slot] = make_float4(x, y, z, nh);
}

__device__ __forceinline__ float cube_bound(
    float px, float py, float pz, int cx, int cy, int cz, int r)
{
    float b = CUDART_INF_F;
    if (cx - r > 0)     b = fminf(b, px - (-RANGE + (float)(cx - r) * H));
    if (cx + r < G - 1) b = fminf(b, (-RANGE + (float)(cx + r + 1) * H) - px);
    if (cy - r > 0)     b = fminf(b, py - (-RANGE + (float)(cy - r) * H));
    if (cy + r < G - 1) b = fminf(b, (-RANGE + (float)(cy + r + 1) * H) - py);
    if (cz - r > 0)     b = fminf(b, pz - (-RANGE + (float)(cz - r) * H));
    if (cz + r < G - 1) b = fminf(b, (-RANGE + (float)(cz + r + 1) * H) - pz);
    return fmaxf(b * 0.9999f, 0.0f);
}

__global__ __launch_bounds__(QBLK) void k_query(float* __restrict__ out)
{
    const int lane = threadIdx.x & 31;
    const int j    = lane & 7;                          // lane within group
    const int qid  = blockIdx.x * QPB + (threadIdx.x >> 3);

    int s_own, u;
    float scale;
    if (qid < 65536) {
        s_own = qid >> 13;
        u     = qid & 8191;
        scale = 0.3f / (4.0f * 8192.0f);
    } else {
        const int tf = qid - 65536;
        s_own = 8 + (tf >> 12);
        u     = tf & 4095;
        scale = 0.7f / (4.0f * 4096.0f);
    }
    const int s = s_own ^ 4;

    const float4 p  = g_pts[s_own * CAP + u];
    const float px = p.x, py = p.y, pz = p.z;
    const float p2 = -2.0f * p.w;

    const float rx = (px + RANGE) * INVH;
    const float ry = (py + RANGE) * INVH;
    const float rz = (pz + RANGE) * INVH;
    const float fx = floorf(rx), fy = floorf(ry), fz = floorf(rz);
    const int cx = min(max((int)fx, 0), G - 1);
    const int cy = min(max((int)fy, 0), G - 1);
    const int cz = min(max((int)fz, 0), G - 1);
    const int lox = min(max((rx - fx >= 0.5f) ? cx : cx - 1, 0), G - 2);
    const int loy = min(max((ry - fy >= 0.5f) ? cy : cy - 1, 0), G - 2);
    const int loz = min(max((rz - fz >= 0.5f) ? cz : cz - 1, 0), G - 2);

    const int*    st  = g_start + s * NCELL;
    const int*    cu  = g_cur   + s * NCELL;
    const float4* pts = g_pts   + s * CAP;

    float m = -CUDART_INF_F;

    // ---- Phase A: 2x2x2 window; 8 lanes = 4 beg + 4 end range loads ----
    {
        const int k  = j & 3;
        const int rb = ((loz + (k >> 1)) * G + (loy + (k & 1))) * G;
        const int rv = (j < 4) ? st[rb + lox] : cu[rb + lox + 1];

        // group-local (width 8): cnt on j<4, then 4-element inclusive scan
        const int endv = __shfl_down_sync(FULL, rv, 4, 8);
        const int cnt  = endv - rv;                    // valid on j<4
        int incl = cnt;
        {
            int t2 = __shfl_up_sync(FULL, incl, 1, 8);
            if (j >= 1) incl += t2;
            t2 = __shfl_up_sync(FULL, incl, 2, 8);
            if (j >= 2) incl += t2;
        }
        const int dl = rv - (incl - cnt);              // valid on j<4

        const int off1 = __shfl_sync(FULL, incl, 0, 8);
        const int off2 = __shfl_sync(FULL, incl, 1, 8);
        const int off3 = __shfl_sync(FULL, incl, 2, 8);
        const int T    = __shfl_sync(FULL, incl, 3, 8);
        const int dl0  = __shfl_sync(FULL, dl, 0, 8);
        const int dl1  = __shfl_sync(FULL, dl, 1, 8);
        const int dl2  = __shfl_sync(FULL, dl, 2, 8);
        const int dl3  = __shfl_sync(FULL, dl, 3, 8);

        int idx = j;
        for (; idx + 8 < T; idx += 16) {
            {
                const int d = (idx < off2) ? ((idx < off1) ? dl0 : dl1)
                                           : ((idx < off3) ? dl2 : dl3);
                const float4 q = pts[idx + d];
                m = fmaxf(m, fmaf(px, q.x, fmaf(py, q.y, fmaf(pz, q.z, q.w))));
            }
            {
                const int jj = idx + 8;
                const int d = (jj < off2) ? ((jj < off1) ? dl0 : dl1)
                                          : ((jj < off3) ? dl2 : dl3);
                const float4 q = pts[jj + d];
                m = fmaxf(m, fmaf(px, q.x, fmaf(py, q.y, fmaf(pz, q.z, q.w))));
            }
        }
        if (idx < T) {
            const int d = (idx < off2) ? ((idx < off1) ? dl0 : dl1)
                                       : ((idx < off3) ? dl2 : dl3);
            const float4 q = pts[idx + d];
            m = fmaxf(m, fmaf(px, q.x, fmaf(py, q.y, fmaf(pz, q.z, q.w))));
        }
    }
    // group max (width 8)
    m = fmaxf(m, __shfl_xor_sync(FULL, m, 4, 8));
    m = fmaxf(m, __shfl_xor_sync(FULL, m, 2, 8));
    m = fmaxf(m, __shfl_xor_sync(FULL, m, 1, 8));
    float bd2 = fmaf(-2.0f, m, p2);

    // exact margin to window faces (inf on domain-clamped sides)
    float b1 = CUDART_INF_F;
    if (lox > 0)         b1 = fminf(b1, px - (-RANGE + (float)lox * H));
    if (lox + 1 < G - 1) b1 = fminf(b1, (-RANGE + (float)(lox + 2) * H) - px);
    if (loy > 0)         b1 = fminf(b1, py - (-RANGE + (float)loy * H));
    if (loy + 1 < G - 1) b1 = fminf(b1, (-RANGE + (float)(loy + 2) * H) - py);
    if (loz > 0)         b1 = fminf(b1, pz - (-RANGE + (float)loz * H));
    if (loz + 1 < G - 1) b1 = fminf(b1, (-RANGE + (float)(loz + 2) * H) - pz);
    b1 = fmaxf(b1 * 0.9999f, 0.0f);

    // ---- Phase B (rare): warp-wide per flagged group, via ballot ----
    const bool needB = bd2 > b1 * b1;                 // group-uniform
    unsigned bm = __ballot_sync(FULL, needB && (j == 0));
    while (bm) {
        const int src = __ffs(bm) - 1;                // leader lane of group
        bm &= bm - 1;

        const float qpx = __shfl_sync(FULL, px, src);
        const float qpy = __shfl_sync(FULL, py, src);
        const float qpz = __shfl_sync(FULL, pz, src);
        const float qp2 = __shfl_sync(FULL, p2, src);
        const int   qcx = __shfl_sync(FULL, cx, src);
        const int   qcy = __shfl_sync(FULL, cy, src);
        const int   qcz = __shfl_sync(FULL, cz, src);
        float qm   = __shfl_sync(FULL, m, src);
        float qbd2 = __shfl_sync(FULL, bd2, src);

        // full 3x3x3 rescan (idempotent)
        {
            const int x0 = max(qcx - 1, 0), x1 = min(qcx + 1, G - 1);
            int beg = 0, end = 0;
            if (lane < 9) {
                const int zz = min(max(qcz + lane / 3 - 1, 0), G - 1);
                const int yy = min(max(qcy + lane % 3 - 1, 0), G - 1);
                const int rb = (zz * G + yy) * G;
                beg = st[rb + x0];
                end = cu[rb + x1];
            }
            float ml = qm;
            #pragma unroll
            for (int k = 0; k < 9; k++) {
                const int b = __shfl_sync(FULL, beg, k);
                const int e = __shfl_sync(FULL, end, k);
                for (int v = b + lane; v < e; v += 32) {
                    const float4 q = pts[v];
                    ml = fmaxf(ml, fmaf(qpx, q.x, fmaf(qpy, q.y, fmaf(qpz, q.z, q.w))));
                }
            }
            #pragma unroll
            for (int o = 16; o; o >>= 1)
                ml = fmaxf(ml, __shfl_xor_sync(FULL, ml, o));
            qm = ml;
            qbd2 = fmaf(-2.0f, qm, qp2);
        }

        // exact shell expansion
        for (int r = 1; r < G - 1; r++) {
            const float bound = cube_bound(qpx, qpy, qpz, qcx, qcy, qcz, r);
            if (qbd2 <= bound * bound) break;

            const int rs = r + 1;
            const int W  = 2 * rs + 1;
            const int NP = W * W;
            float m2 = qm;
            for (int idx = lane; idx < NP; idx += 32) {
                const int dz = idx / W - rs;
                const int dy = idx - (dz + rs) * W - rs;
                const int zz = qcz + dz;
                const int yy = qcy + dy;
                if (zz < 0 || zz >= G || yy < 0 || yy >= G) continue;
                const int rb = (zz * G + yy) * G;
                if (dz == -rs || dz == rs || dy == -rs || dy == rs) {
                    const int xb = max(qcx - rs, 0), xe = min(qcx + rs, G - 1);
                    const int bb = st[rb + xb], ee = cu[rb + xe];
                    for (int v = bb; v < ee; v++) {
                        const float4 q = pts[v];
                        m2 = fmaxf(m2, fmaf(qpx, q.x, fmaf(qpy, q.y, fmaf(qpz, q.z, q.w))));
                    }
                } else {
                    const int xl = qcx - rs;
                    if (xl >= 0) {
                        const int bb = st[rb + xl], ee = cu[rb + xl];
                        for (int v = bb; v < ee; v++) {
                            const float4 q = pts[v];
                            m2 = fmaxf(m2, fmaf(qpx, q.x, fmaf(qpy, q.y, fmaf(qpz, q.z, q.w))));
                        }
                    }
                    const int xr = qcx + rs;
                    if (xr < G) {
                        const int bb = st[rb + xr], ee = cu[rb + xr];
                        for (int v = bb; v < ee; v++) {
                            const float4 q = pts[v];
                            m2 = fmaxf(m2, fmaf(qpx, q.x, fmaf(qpy, q.y, fmaf(qpz, q.z, q.w))));
                        }
                    }
                }
            }
            #pragma unroll
            for (int o = 16; o; o >>= 1)
                m2 = fmaxf(m2, __shfl_xor_sync(FULL, m2, o));
            qm = m2;
            qbd2 = fmaf(-2.0f, qm, qp2);
        }

        if (lane == src) bd2 = qbd2;                  // write back to leader
    }

    // sum: group leaders contribute bd2*scale; warp reduce; block reduce
    float val = (j == 0) ? bd2 * scale : 0.0f;
    #pragma unroll
    for (int o = 16; o; o >>= 1)
        val += __shfl_xor_sync(FULL, val, o);

    __shared__ float ws[QWARPS];
    if (lane == 0) ws[threadIdx.x >> 5] = val;
    __syncthreads();
    if (threadIdx.x == 0) {
        float v = 0.0f;
        #pragma unroll
        for (int w = 0; w < QWARPS; w++) v += ws[w];
        atomicAdd(out, v);
    }
}

extern "C" void kernel_launch(void* const* d_in, const int* in_sizes, int n_in,
                              void* d_out, int out_size) {
    const float* pf = (const float*)d_in[0];
    const float* gf = (const float*)d_in[1];
    const float* pn = (const float*)d_in[2];
    const float* gn = (const float*)d_in[3];
    float* out = (float*)d_out;

    // g_cnt zeroed at module load and re-zeroed by k_scan every call.
    k_count<<<NQ_TOTAL / 256, 256>>>(pf, gf, pn, gn);     // launch 0
    k_scan<<<NSTRUCT, 1024>>>(out);                       // launch 1
    k_scatter<<<NQ_TOTAL / 256, 256>>>(pf, gf, pn, gn);   // launch 2
    k_query<<<QBLOCKS, QBLK>>>(out);                      // launch 3 (ncu slot)
}